// round 1
// baseline (speedup 1.0000x reference)
#include <cuda_runtime.h>
#include <math.h>

#define BATCH 8
#define PRI   24564
#define NC    80        // classes 1..80 (channel slots)
#define CDIM  93
#define TK1   400
#define TK2   200
#define NDET  (NC*TK1)  // 32000
#define OGRID 19
#define NWORD 7         // ceil(400/64)

// ---------------- scratch (device globals; no allocation allowed) ----------------
__device__ float4       g_boxes[BATCH*PRI];
__device__ unsigned int g_keys[(size_t)BATCH*NC*PRI];    // transformed masked conf, [b][c][p]
__device__ float        g_selScore[BATCH*NC*TK1];
__device__ int          g_selIdx[BATCH*NC*TK1];
__device__ unsigned int g_detKey[BATCH*NDET];            // transformed det score per (b, c*400+r)
__device__ float        g_topS[BATCH*TK2];
__device__ int          g_topFi[BATCH*TK2];

// order-preserving float<->uint transform (total order, -1 < all positives)
__device__ __forceinline__ unsigned f2u(float f){
    unsigned u = __float_as_uint(f);
    return (u & 0x80000000u) ? ~u : (u | 0x80000000u);
}
__device__ __forceinline__ float u2f(unsigned u){
    return (u & 0x80000000u) ? __uint_as_float(u & 0x7FFFFFFFu) : __uint_as_float(~u);
}

// precise expf even if harness compiles with fast-math
__device__ __forceinline__ float exp_precise(float a){
#if defined(__USE_FAST_MATH__) || defined(__FAST_MATH__)
    return (float)exp((double)a);
#else
    return expf(a);
#endif
}

// ---------------- K1: decode boxes + transpose masked conf into keys ----------------
__global__ void k_decode(const float* __restrict__ x){
    __shared__ float tile[64*CDIM];
    int b   = blockIdx.y;
    int pb  = blockIdx.x * 64;
    int cnt = min(64, PRI - pb);
    int tid = threadIdx.x, bd = blockDim.x;
    const float* src = x + ((size_t)b*PRI + pb)*CDIM;
    for (int i = tid; i < cnt*CDIM; i += bd) tile[i] = src[i];
    __syncthreads();
    if (tid < cnt){
        const float* r = &tile[tid*CDIM];
        float l0=r[0], l1=r[1], l2=r[2], l3=r[3];
        float q0=r[85], q1=r[86], q2=r[87], q3=r[88];
        float v0=r[89], v1=r[90], v2=r[91], v3=r[92];
        float pw  = __fsub_rn(q2,q0), ph = __fsub_rn(q3,q1);
        float pcx = __fmul_rn(0.5f, __fadd_rn(q2,q0));
        float pcy = __fmul_rn(0.5f, __fadd_rn(q3,q1));
        float cx  = __fadd_rn(__fmul_rn(__fmul_rn(l0,pw), v0), pcx);
        float cy  = __fadd_rn(__fmul_rn(__fmul_rn(l1,pw), v1), pcy);  // ref uses pw for cy too
        float w   = __fmul_rn(exp_precise(__fmul_rn(l2,v2)), pw);
        float h   = __fmul_rn(exp_precise(__fmul_rn(l3,v3)), ph);
        float4 bx;
        bx.x = fminf(fmaxf(__fsub_rn(cx, __fmul_rn(0.5f,w)), 0.f), 1.f);
        bx.y = fminf(fmaxf(__fsub_rn(cy, __fmul_rn(0.5f,h)), 0.f), 1.f);
        bx.z = fminf(fmaxf(__fadd_rn(cx, __fmul_rn(0.5f,w)), 0.f), 1.f);
        bx.w = fminf(fmaxf(__fadd_rn(cy, __fmul_rn(0.5f,h)), 0.f), 1.f);
        g_boxes[(size_t)b*PRI + pb + tid] = bx;
    }
    for (int j = tid; j < NC*64; j += bd){
        int c = j >> 6, pl = j & 63;
        if (pl < cnt){
            float v = tile[pl*CDIM + 5 + c];
            g_keys[((size_t)(b*NC + c))*PRI + pb + pl] =
                (v > 0.01f) ? f2u(v) : 0x407FFFFFu;   // f2u(-1.0f)
        }
    }
}

// ---------------- block-wide exact top-K select (512 threads required) ----------------
// keys64 out: top K sorted descending by (value, ~index); rest padded with 0.
__device__ void block_topk(const unsigned* __restrict__ gvals, int N, int K,
                           unsigned* svals, unsigned long long* keys, unsigned* hist)
{
    const int tid = threadIdx.x, bd = blockDim.x;
    for (int i = tid; i < N;   i += bd) svals[i] = gvals[i];
    for (int i = tid; i < 512; i += bd) keys[i]  = 0ULL;

    __shared__ unsigned s_prefix;
    __shared__ int s_k, s_above, s_cnt, s_eqbase;
    __shared__ int warpTot[16];
    if (tid == 0){ s_prefix = 0u; s_k = K; s_above = 0; s_cnt = 0; s_eqbase = 0; }
    __syncthreads();

    // 4-level radix select on value
    for (int shift = 24; shift >= 0; shift -= 8){
        for (int i = tid; i < 256; i += bd) hist[i] = 0;
        __syncthreads();
        unsigned pmask = (shift == 24) ? 0u : (0xFFFFFFFFu << (shift+8));
        unsigned pref  = s_prefix;
        for (int i = tid; i < N; i += bd){
            unsigned v = svals[i];
            if ((v & pmask) == pref) atomicAdd(&hist[(v >> shift) & 255u], 1u);
        }
        __syncthreads();
        if (tid == 0){
            int k = s_k, cum = 0, bsel = 0;
            for (int bn = 255; bn >= 0; bn--){
                int c = (int)hist[bn];
                if (cum + c >= k){ bsel = bn; break; }
                cum += c;
            }
            s_prefix = pref | ((unsigned)bsel << shift);
            s_k      = k - cum;
            s_above += cum;
        }
        __syncthreads();
    }
    const unsigned T  = s_prefix;
    const int need     = s_k;       // # of ==T elements to take (lowest index first)
    const int cntAbove = s_above;   // # strictly above T

    // compact strictly-above (unordered; sort fixes order)
    for (int i = tid; i < N; i += bd){
        unsigned v = svals[i];
        if (v > T){
            int pos = atomicAdd(&s_cnt, 1);
            keys[pos] = ((unsigned long long)v << 32) | (unsigned)(~(unsigned)i);
        }
    }
    __syncthreads();

    // equal-to-T in index order, take `need`
    int lane = tid & 31, wid = tid >> 5;
    for (int base = 0; base < N && s_eqbase < need; base += bd){
        int i = base + tid;
        bool eq = (i < N) && (svals[i] == T);
        unsigned ball = __ballot_sync(0xFFFFFFFFu, eq);
        int wpre = __popc(ball & ((1u << lane) - 1u));
        if (lane == 0) warpTot[wid] = __popc(ball);
        __syncthreads();
        int pre = 0;
        for (int w = 0; w < wid; w++) pre += warpTot[w];
        int rank = s_eqbase + pre + wpre;
        if (eq && rank < need)
            keys[cntAbove + rank] = ((unsigned long long)T << 32) | (unsigned)(~(unsigned)i);
        __syncthreads();
        if (tid == 0){ int tot = 0; for (int w = 0; w < 16; w++) tot += warpTot[w]; s_eqbase += tot; }
        __syncthreads();
    }
    __syncthreads();

    // bitonic sort, 512 elements, descending
    for (unsigned size = 2; size <= 512; size <<= 1){
        for (unsigned stride = size >> 1; stride > 0; stride >>= 1){
            __syncthreads();
            unsigned i = tid, j = i ^ stride;
            if (j > i){
                unsigned long long a = keys[i], bb = keys[j];
                bool up = ((i & size) == 0);
                if (up ? (a < bb) : (a > bb)){ keys[i] = bb; keys[j] = a; }
            }
        }
    }
    __syncthreads();
}

// ---------------- K2: per-(b,c) top-400 ----------------
__global__ void k_select_class(){
    extern __shared__ unsigned dynv[];
    __shared__ unsigned long long keys[512];
    __shared__ unsigned hist[256];
    int bc = blockIdx.x;
    block_topk(g_keys + (size_t)bc*PRI, PRI, TK1, dynv, keys, hist);
    for (int r = threadIdx.x; r < TK1; r += blockDim.x){
        unsigned long long kk = keys[r];
        g_selScore[bc*TK1 + r] = u2f((unsigned)(kk >> 32));
        g_selIdx  [bc*TK1 + r] = (int)(~(unsigned)(kk & 0xFFFFFFFFu));
    }
}

// ---------------- K3: greedy NMS per (b,c) ----------------
__global__ void k_nms(){
    __shared__ float4 sbox[TK1];
    __shared__ float  sarea[TK1];
    __shared__ float  sS[TK1];
    __shared__ unsigned long long smat[TK1*NWORD];
    __shared__ unsigned long long skept[NWORD];
    int bc = blockIdx.x, b = bc / NC, c = bc % NC;
    int tid = threadIdx.x, bd = blockDim.x;

    for (int r = tid; r < TK1; r += bd){
        float sc = g_selScore[bc*TK1 + r];
        int  idx = g_selIdx  [bc*TK1 + r];
        float4 bx = g_boxes[(size_t)b*PRI + idx];
        sbox[r] = bx; sS[r] = sc;
        sarea[r] = __fmul_rn(__fsub_rn(bx.z,bx.x), __fsub_rn(bx.w,bx.y));
    }
    __syncthreads();

    // lower-triangle suppression bitmatrix: bit (i,j) = iou(i,j) > 0.45, j < i
    for (int t = tid; t < TK1*NWORD; t += bd){
        int i = t / NWORD, w = t % NWORD;
        int j0 = w*64, j1 = min(i, j0 + 64);
        unsigned long long word = 0;
        if (j1 > j0){
            float4 a = sbox[i]; float ai = sarea[i];
            for (int j = j0; j < j1; j++){
                float4 d = sbox[j];
                float ix1 = fmaxf(a.x, d.x), iy1 = fmaxf(a.y, d.y);
                float ix2 = fminf(a.z, d.z), iy2 = fminf(a.w, d.w);
                float iw = fmaxf(__fsub_rn(ix2, ix1), 0.0f);
                float ih = fmaxf(__fsub_rn(iy2, iy1), 0.0f);
                float inter = __fmul_rn(iw, ih);
                bool gt = false;
                if (inter > 0.0f){
                    float uni = __fsub_rn(__fadd_rn(ai, sarea[j]), inter);
                    if (uni > 0.0f){
                        if (inter > 0.46f*uni)       gt = true;
                        else if (inter >= 0.44f*uni) gt = (__fdiv_rn(inter, uni) > 0.45f);
                    }
                }
                if (gt) word |= 1ULL << (j - j0);
            }
        }
        smat[i*NWORD + w] = word;
    }
    __syncthreads();

    // sequential greedy scan (warp 0, 7 lanes hold kept words)
    if (tid < 32){
        unsigned long long keptw = 0;
        for (int i = 0; i < TK1; i++){
            unsigned long long m = (tid < NWORD) ? (smat[i*NWORD + tid] & keptw) : 0ULL;
            bool any = __any_sync(0xFFFFFFFFu, m != 0ULL);
            bool keep = (sS[i] > 0.01f) && !any;
            if (keep && tid == (i >> 6)) keptw |= 1ULL << (i & 63);
        }
        if (tid < NWORD) skept[tid] = keptw;
    }
    __syncthreads();

    for (int r = tid; r < TK1; r += bd){
        bool kept = (skept[r >> 6] >> (r & 63)) & 1ULL;
        float sc = kept ? sS[r] : -1.0f;
        g_detKey[(size_t)b*NDET + c*TK1 + r] = f2u(sc);
    }
}

// ---------------- K4: per-batch top-200 over 32000 dets ----------------
__global__ void k_select_det(){
    extern __shared__ unsigned dynv[];
    __shared__ unsigned long long keys[512];
    __shared__ unsigned hist[256];
    int b = blockIdx.x;
    block_topk(g_detKey + (size_t)b*NDET, NDET, TK2, dynv, keys, hist);
    for (int r = threadIdx.x; r < TK2; r += blockDim.x){
        unsigned long long kk = keys[r];
        g_topS [b*TK2 + r] = u2f((unsigned)(kk >> 32));
        g_topFi[b*TK2 + r] = (int)(~(unsigned)(kk & 0xFFFFFFFFu));
    }
}

// ---------------- K5: rasterize ----------------
__global__ void k_raster(float* __restrict__ out){
    __shared__ float sS2[TK2];
    __shared__ int   sCh[TK2];
    __shared__ int4  sCo[TK2];
    __shared__ unsigned char sV[TK2];
    int b = blockIdx.x, tid = threadIdx.x;

    for (int k = tid; k < TK2; k += blockDim.x){
        float s = g_topS[b*TK2 + k];
        int  fi = g_topFi[b*TK2 + k];
        int  c  = fi / TK1, r = fi % TK1;
        int idx = g_selIdx[(b*NC + c)*TK1 + r];
        float4 bx = g_boxes[(size_t)b*PRI + idx];
        int4 co;
        co.x = (int)rintf(__fmul_rn(bx.x, (float)OGRID));
        co.y = (int)rintf(__fmul_rn(bx.y, (float)OGRID));
        co.z = (int)rintf(__fmul_rn(bx.z, (float)OGRID));
        co.w = (int)rintf(__fmul_rn(bx.w, (float)OGRID));
        sS2[k] = s; sCh[k] = c; sCo[k] = co; sV[k] = (s >= 0.6f) ? 1 : 0;
    }
    __syncthreads();

    for (int cell = tid; cell < OGRID*OGRID; cell += blockDim.x){
        int y = cell / OGRID, xp = cell % OGRID;
        float* o = out + ((size_t)b*OGRID*OGRID + cell) * 81;
        for (int ch = 0; ch < 81; ch++) o[ch] = 0.0f;
        for (int k = 0; k < TK2; k++){
            if (sV[k]){
                int4 co = sCo[k];
                if (y >= co.y && y < co.w && xp >= co.x && xp < co.z)
                    o[sCh[k]] = sS2[k];     // ascending k: last writer == max k
            }
        }
    }
}

// ---------------- launch ----------------
extern "C" void kernel_launch(void* const* d_in, const int* in_sizes, int n_in,
                              void* d_out, int out_size){
    const float* x = (const float*)d_in[0];
    float* out = (float*)d_out;
    cudaFuncSetAttribute(k_select_class, cudaFuncAttributeMaxDynamicSharedMemorySize, PRI*(int)sizeof(unsigned));
    cudaFuncSetAttribute(k_select_det,   cudaFuncAttributeMaxDynamicSharedMemorySize, NDET*(int)sizeof(unsigned));

    dim3 g1((PRI + 63) / 64, BATCH);
    k_decode<<<g1, 128>>>(x);
    k_select_class<<<BATCH*NC, 512, PRI*sizeof(unsigned)>>>();
    k_nms<<<BATCH*NC, 256>>>();
    k_select_det<<<BATCH, 512, NDET*sizeof(unsigned)>>>();
    k_raster<<<BATCH, 512>>>(out);
}

// round 2
// speedup vs baseline: 1.0214x; 1.0214x over previous
#include <cuda_runtime.h>
#include <math.h>

#define BATCH 8
#define PRI   24564
#define NC    80        // classes 1..80 (channel slots)
#define CDIM  93
#define TK1   400
#define TK2   200
#define NDET  (NC*TK1)  // 32000
#define OGRID 19
#define NWORD 7         // ceil(400/64)

// ---------------- scratch (device globals; no allocation allowed) ----------------
__device__ float4       g_boxes[BATCH*PRI];
__device__ unsigned int g_keys[(size_t)BATCH*NC*PRI];    // transformed masked conf, [b][c][p]
__device__ float        g_selScore[BATCH*NC*TK1];
__device__ int          g_selIdx[BATCH*NC*TK1];
__device__ unsigned int g_detKey[BATCH*NDET];            // transformed det score per (b, c*400+r)
__device__ float        g_topS[BATCH*TK2];
__device__ int          g_topFi[BATCH*TK2];

// order-preserving float<->uint transform (total order, -1 < all positives)
__device__ __forceinline__ unsigned f2u(float f){
    unsigned u = __float_as_uint(f);
    return (u & 0x80000000u) ? ~u : (u | 0x80000000u);
}
__device__ __forceinline__ float u2f(unsigned u){
    return (u & 0x80000000u) ? __uint_as_float(u & 0x7FFFFFFFu) : __uint_as_float(~u);
}

// precise expf even if harness compiles with fast-math
__device__ __forceinline__ float exp_precise(float a){
#if defined(__USE_FAST_MATH__) || defined(__FAST_MATH__)
    return (float)exp((double)a);
#else
    return expf(a);
#endif
}

// ---------------- K1: decode boxes + transpose masked conf into keys ----------------
__global__ void k_decode(const float* __restrict__ x){
    __shared__ float tile[64*CDIM];
    int b   = blockIdx.y;
    int pb  = blockIdx.x * 64;
    int cnt = min(64, PRI - pb);
    int tid = threadIdx.x, bd = blockDim.x;
    const float* src = x + ((size_t)b*PRI + pb)*CDIM;
    for (int i = tid; i < cnt*CDIM; i += bd) tile[i] = src[i];
    __syncthreads();
    if (tid < cnt){
        const float* r = &tile[tid*CDIM];
        float l0=r[0], l1=r[1], l2=r[2], l3=r[3];
        float q0=r[85], q1=r[86], q2=r[87], q3=r[88];
        float v0=r[89], v1=r[90], v2=r[91], v3=r[92];
        float pw  = __fsub_rn(q2,q0), ph = __fsub_rn(q3,q1);
        float pcx = __fmul_rn(0.5f, __fadd_rn(q2,q0));
        float pcy = __fmul_rn(0.5f, __fadd_rn(q3,q1));
        float cx  = __fadd_rn(__fmul_rn(__fmul_rn(l0,pw), v0), pcx);
        float cy  = __fadd_rn(__fmul_rn(__fmul_rn(l1,pw), v1), pcy);  // ref uses pw for cy too
        float w   = __fmul_rn(exp_precise(__fmul_rn(l2,v2)), pw);
        float h   = __fmul_rn(exp_precise(__fmul_rn(l3,v3)), ph);
        float4 bx;
        bx.x = fminf(fmaxf(__fsub_rn(cx, __fmul_rn(0.5f,w)), 0.f), 1.f);
        bx.y = fminf(fmaxf(__fsub_rn(cy, __fmul_rn(0.5f,h)), 0.f), 1.f);
        bx.z = fminf(fmaxf(__fadd_rn(cx, __fmul_rn(0.5f,w)), 0.f), 1.f);
        bx.w = fminf(fmaxf(__fadd_rn(cy, __fmul_rn(0.5f,h)), 0.f), 1.f);
        g_boxes[(size_t)b*PRI + pb + tid] = bx;
    }
    for (int j = tid; j < NC*64; j += bd){
        int c = j >> 6, pl = j & 63;
        if (pl < cnt){
            float v = tile[pl*CDIM + 5 + c];
            g_keys[((size_t)(b*NC + c))*PRI + pb + pl] =
                (v > 0.01f) ? f2u(v) : 0x407FFFFFu;   // f2u(-1.0f)
        }
    }
}

// ---------------- block-wide exact top-K select (512 threads required) ----------------
// keys out: top K sorted descending by (value, ~index) packed u64; rest padded with 0.
__device__ void block_topk(const unsigned* __restrict__ gvals, int N, int K,
                           unsigned* svals, unsigned long long* keys)
{
    __shared__ unsigned whist[16*256];    // per-warp histograms
    __shared__ unsigned suf[256];         // suffix sums
    __shared__ unsigned s_prefix;
    __shared__ int s_k, s_above, s_cnt, s_eq, s_eqbase;
    __shared__ int warpTot[16];
    const int tid = threadIdx.x, bd = blockDim.x;
    const int wid = tid >> 5, lane = tid & 31;

    for (int i = tid; i < N;   i += bd) svals[i] = gvals[i];
    for (int i = tid; i < 512; i += bd) keys[i]  = 0ULL;
    if (tid == 0){ s_prefix = 0u; s_k = K; s_above = 0; s_cnt = 0; s_eq = 0; s_eqbase = 0; }
    __syncthreads();

    // 4-level radix select on value, per-warp privatized histograms
    for (int shift = 24; shift >= 0; shift -= 8){
        for (int i = tid; i < 16*256; i += bd) whist[i] = 0u;
        __syncthreads();
        unsigned pmask = (shift == 24) ? 0u : (0xFFFFFFFFu << (shift+8));
        unsigned pref  = s_prefix;
        unsigned* myh  = &whist[wid << 8];
        for (int i = tid; i < N; i += bd){
            unsigned v = svals[i];
            if ((v & pmask) == pref) atomicAdd(&myh[(v >> shift) & 255u], 1u);
        }
        __syncthreads();
        if (tid < 256){
            unsigned s = 0;
            #pragma unroll
            for (int w = 0; w < 16; w++) s += whist[(w << 8) + tid];
            suf[tid] = s;
        }
        __syncthreads();
        // suffix sums (from the top): suf[bn] = count of bins >= bn
        for (int off = 1; off < 256; off <<= 1){
            unsigned add = (tid < 256 && tid + off < 256) ? suf[tid + off] : 0u;
            __syncthreads();
            if (tid < 256) suf[tid] += add;
            __syncthreads();
        }
        int k = s_k;
        __syncthreads();   // everyone snapshots k before the single writer mutates it
        if (tid < 256){
            int here  = (int)suf[tid];
            int above = (tid == 255) ? 0 : (int)suf[tid+1];
            if (here >= k && above < k){    // unique crossing: bsel = tid
                s_prefix = pref | ((unsigned)tid << shift);
                s_k      = k - above;
                s_above += above;
            }
        }
        __syncthreads();
    }
    const unsigned T   = s_prefix;
    const int need     = s_k;       // # of ==T elements to take (lowest index first)
    const int cntAbove = s_above;   // # strictly above T

    // compact strictly-above (unordered; sort fixes order)
    for (int i = tid; i < N; i += bd){
        unsigned v = svals[i];
        if (v > T){
            int pos = atomicAdd(&s_cnt, 1);
            keys[pos] = ((unsigned long long)v << 32) | (unsigned)(~(unsigned)i);
        }
    }
    // collect ==T indices (unordered) into reused whist buffer
    unsigned* idxbuf = whist;   // capacity 4096
    for (int i = tid; i < N; i += bd){
        if (svals[i] == T){
            int p = atomicAdd(&s_eq, 1);
            if (p < 4096) idxbuf[p] = (unsigned)i;
        }
    }
    __syncthreads();
    int E = s_eq;
    if (E <= need){
        // E == need by construction: every ==T element is selected; order is
        // irrelevant here, the bitonic sort below orders by (value, ~index).
        for (int p = tid; p < E; p += bd)
            keys[cntAbove + p] = ((unsigned long long)T << 32) | (unsigned)(~idxbuf[p]);
        __syncthreads();
    } else {
        // rare fallback (many exact ties at T): chunked index-ordered scan
        for (int base = 0; base < N && s_eqbase < need; base += bd){
            int i = base + tid;
            bool eq = (i < N) && (svals[i] == T);
            unsigned ball = __ballot_sync(0xFFFFFFFFu, eq);
            int wpre = __popc(ball & ((1u << lane) - 1u));
            if (lane == 0) warpTot[wid] = __popc(ball);
            __syncthreads();
            int pre = 0;
            for (int w = 0; w < wid; w++) pre += warpTot[w];
            int rank = s_eqbase + pre + wpre;
            if (eq && rank < need)
                keys[cntAbove + rank] = ((unsigned long long)T << 32) | (unsigned)(~(unsigned)i);
            __syncthreads();
            if (tid == 0){ int tot = 0; for (int w = 0; w < 16; w++) tot += warpTot[w]; s_eqbase += tot; }
            __syncthreads();
        }
        __syncthreads();
    }

    // bitonic sort, 512 elements, descending
    for (unsigned size = 2; size <= 512; size <<= 1){
        for (unsigned stride = size >> 1; stride > 0; stride >>= 1){
            __syncthreads();
            unsigned i = tid, j = i ^ stride;
            if (j > i){
                unsigned long long a = keys[i], bb = keys[j];
                bool up = ((i & size) == 0);
                if (up ? (a < bb) : (a > bb)){ keys[i] = bb; keys[j] = a; }
            }
        }
    }
    __syncthreads();
}

// ---------------- K2: per-(b,c) top-400 ----------------
__global__ void k_select_class(){
    extern __shared__ unsigned dynv[];
    __shared__ unsigned long long keys[512];
    int bc = blockIdx.x;
    block_topk(g_keys + (size_t)bc*PRI, PRI, TK1, dynv, keys);
    for (int r = threadIdx.x; r < TK1; r += blockDim.x){
        unsigned long long kk = keys[r];
        g_selScore[bc*TK1 + r] = u2f((unsigned)(kk >> 32));
        g_selIdx  [bc*TK1 + r] = (int)(~(unsigned)(kk & 0xFFFFFFFFu));
    }
}

// ---------------- K3: greedy NMS per (b,c) ----------------
__global__ void k_nms(){
    __shared__ float4 sbox[TK1];
    __shared__ float  sarea[TK1];
    __shared__ float  sS[TK1];
    __shared__ unsigned long long smat[TK1*NWORD];
    __shared__ unsigned long long skept[NWORD];
    int bc = blockIdx.x, b = bc / NC, c = bc % NC;
    int tid = threadIdx.x, bd = blockDim.x;

    for (int r = tid; r < TK1; r += bd){
        float sc = g_selScore[bc*TK1 + r];
        int  idx = g_selIdx  [bc*TK1 + r];
        float4 bx = g_boxes[(size_t)b*PRI + idx];
        sbox[r] = bx; sS[r] = sc;
        sarea[r] = __fmul_rn(__fsub_rn(bx.z,bx.x), __fsub_rn(bx.w,bx.y));
    }
    __syncthreads();

    // lower-triangle suppression bitmatrix: bit (i,j) = iou(i,j) > 0.45, j < i
    for (int t = tid; t < TK1*NWORD; t += bd){
        int i = t / NWORD, w = t % NWORD;
        int j0 = w*64, j1 = min(i, j0 + 64);
        unsigned long long word = 0;
        if (j1 > j0){
            float4 a = sbox[i]; float ai = sarea[i];
            for (int j = j0; j < j1; j++){
                float4 d = sbox[j];
                float ix1 = fmaxf(a.x, d.x), iy1 = fmaxf(a.y, d.y);
                float ix2 = fminf(a.z, d.z), iy2 = fminf(a.w, d.w);
                float iw = fmaxf(__fsub_rn(ix2, ix1), 0.0f);
                float ih = fmaxf(__fsub_rn(iy2, iy1), 0.0f);
                float inter = __fmul_rn(iw, ih);
                bool gt = false;
                if (inter > 0.0f){
                    float uni = __fsub_rn(__fadd_rn(ai, sarea[j]), inter);
                    if (uni > 0.0f){
                        if (inter > 0.46f*uni)       gt = true;
                        else if (inter >= 0.44f*uni) gt = (__fdiv_rn(inter, uni) > 0.45f);
                    }
                }
                if (gt) word |= 1ULL << (j - j0);
            }
        }
        smat[i*NWORD + w] = word;
    }
    __syncthreads();

    // sequential greedy scan (warp 0, 7 lanes hold kept words)
    if (tid < 32){
        unsigned long long keptw = 0;
        for (int i = 0; i < TK1; i++){
            unsigned long long m = (tid < NWORD) ? (smat[i*NWORD + tid] & keptw) : 0ULL;
            bool any = __any_sync(0xFFFFFFFFu, m != 0ULL);
            bool keep = (sS[i] > 0.01f) && !any;
            if (keep && tid == (i >> 6)) keptw |= 1ULL << (i & 63);
        }
        if (tid < NWORD) skept[tid] = keptw;
    }
    __syncthreads();

    for (int r = tid; r < TK1; r += bd){
        bool kept = (skept[r >> 6] >> (r & 63)) & 1ULL;
        float sc = kept ? sS[r] : -1.0f;
        g_detKey[(size_t)b*NDET + c*TK1 + r] = f2u(sc);
    }
}

// ---------------- K4: per-batch top-200 over 32000 dets ----------------
__global__ void k_select_det(){
    extern __shared__ unsigned dynv[];
    __shared__ unsigned long long keys[512];
    int b = blockIdx.x;
    block_topk(g_detKey + (size_t)b*NDET, NDET, TK2, dynv, keys);
    for (int r = threadIdx.x; r < TK2; r += blockDim.x){
        unsigned long long kk = keys[r];
        g_topS [b*TK2 + r] = u2f((unsigned)(kk >> 32));
        g_topFi[b*TK2 + r] = (int)(~(unsigned)(kk & 0xFFFFFFFFu));
    }
}

// ---------------- K5: rasterize ----------------
__global__ void k_raster(float* __restrict__ out){
    __shared__ float sS2[TK2];
    __shared__ int   sCh[TK2];
    __shared__ int4  sCo[TK2];
    __shared__ unsigned char sV[TK2];
    int b = blockIdx.x, tid = threadIdx.x;

    for (int k = tid; k < TK2; k += blockDim.x){
        float s = g_topS[b*TK2 + k];
        int  fi = g_topFi[b*TK2 + k];
        int  c  = fi / TK1, r = fi % TK1;
        int idx = g_selIdx[(b*NC + c)*TK1 + r];
        float4 bx = g_boxes[(size_t)b*PRI + idx];
        int4 co;
        co.x = (int)rintf(__fmul_rn(bx.x, (float)OGRID));
        co.y = (int)rintf(__fmul_rn(bx.y, (float)OGRID));
        co.z = (int)rintf(__fmul_rn(bx.z, (float)OGRID));
        co.w = (int)rintf(__fmul_rn(bx.w, (float)OGRID));
        sS2[k] = s; sCh[k] = c; sCo[k] = co; sV[k] = (s >= 0.6f) ? 1 : 0;
    }
    __syncthreads();

    for (int cell = tid; cell < OGRID*OGRID; cell += blockDim.x){
        int y = cell / OGRID, xp = cell % OGRID;
        float* o = out + ((size_t)b*OGRID*OGRID + cell) * 81;
        for (int ch = 0; ch < 81; ch++) o[ch] = 0.0f;
        for (int k = 0; k < TK2; k++){
            if (sV[k]){
                int4 co = sCo[k];
                if (y >= co.y && y < co.w && xp >= co.x && xp < co.z)
                    o[sCh[k]] = sS2[k];     // ascending k: last writer == max k
            }
        }
    }
}

// ---------------- launch ----------------
extern "C" void kernel_launch(void* const* d_in, const int* in_sizes, int n_in,
                              void* d_out, int out_size){
    const float* x = (const float*)d_in[0];
    float* out = (float*)d_out;
    cudaFuncSetAttribute(k_select_class, cudaFuncAttributeMaxDynamicSharedMemorySize, PRI*(int)sizeof(unsigned));
    cudaFuncSetAttribute(k_select_det,   cudaFuncAttributeMaxDynamicSharedMemorySize, NDET*(int)sizeof(unsigned));

    dim3 g1((PRI + 63) / 64, BATCH);
    k_decode<<<g1, 128>>>(x);
    k_select_class<<<BATCH*NC, 512, PRI*sizeof(unsigned)>>>();
    k_nms<<<BATCH*NC, 512>>>();
    k_select_det<<<BATCH, 512, NDET*sizeof(unsigned)>>>();
    k_raster<<<BATCH, 512>>>(out);
}

// round 3
// speedup vs baseline: 1.2015x; 1.1763x over previous
#include <cuda_runtime.h>
#include <math.h>

#define BATCH 8
#define PRI   24564
#define NC    80        // classes 1..80 (channel slots)
#define CDIM  93
#define TK1   400
#define TK2   200
#define NDET  (NC*TK1)  // 32000
#define OGRID 19
#define NWORD 7         // ceil(400/64)
#define CAP   2048      // candidate capacity for fast top-k path

// ---------------- scratch (device globals; no allocation allowed) ----------------
__device__ float4       g_boxes[BATCH*PRI];
__device__ unsigned int g_keys[(size_t)BATCH*NC*PRI];    // transformed masked conf, [b][c][p]
__device__ int          g_selIdx[BATCH*NC*TK1];
__device__ unsigned int g_detKey[BATCH*NDET];            // transformed det score per (b, c*400+r)

// order-preserving float<->uint transform (total order, -1 < all positives)
__device__ __forceinline__ unsigned f2u(float f){
    unsigned u = __float_as_uint(f);
    return (u & 0x80000000u) ? ~u : (u | 0x80000000u);
}
__device__ __forceinline__ float u2f(unsigned u){
    return (u & 0x80000000u) ? __uint_as_float(u & 0x7FFFFFFFu) : __uint_as_float(~u);
}

// precise expf even if harness compiles with fast-math
__device__ __forceinline__ float exp_precise(float a){
#if defined(__USE_FAST_MATH__) || defined(__FAST_MATH__)
    return (float)exp((double)a);
#else
    return expf(a);
#endif
}

// ---------------- K1: decode boxes + transpose masked conf into keys ----------------
__global__ void k_decode(const float* __restrict__ x){
    __shared__ float tile[64*CDIM];
    int b   = blockIdx.y;
    int pb  = blockIdx.x * 64;
    int cnt = min(64, PRI - pb);
    int tid = threadIdx.x, bd = blockDim.x;
    const float* src = x + ((size_t)b*PRI + pb)*CDIM;
    for (int i = tid; i < cnt*CDIM; i += bd) tile[i] = src[i];
    __syncthreads();
    if (tid < cnt){
        const float* r = &tile[tid*CDIM];
        float l0=r[0], l1=r[1], l2=r[2], l3=r[3];
        float q0=r[85], q1=r[86], q2=r[87], q3=r[88];
        float v0=r[89], v1=r[90], v2=r[91], v3=r[92];
        float pw  = __fsub_rn(q2,q0), ph = __fsub_rn(q3,q1);
        float pcx = __fmul_rn(0.5f, __fadd_rn(q2,q0));
        float pcy = __fmul_rn(0.5f, __fadd_rn(q3,q1));
        float cx  = __fadd_rn(__fmul_rn(__fmul_rn(l0,pw), v0), pcx);
        float cy  = __fadd_rn(__fmul_rn(__fmul_rn(l1,pw), v1), pcy);  // ref uses pw for cy too
        float w   = __fmul_rn(exp_precise(__fmul_rn(l2,v2)), pw);
        float h   = __fmul_rn(exp_precise(__fmul_rn(l3,v3)), ph);
        float4 bx;
        bx.x = fminf(fmaxf(__fsub_rn(cx, __fmul_rn(0.5f,w)), 0.f), 1.f);
        bx.y = fminf(fmaxf(__fsub_rn(cy, __fmul_rn(0.5f,h)), 0.f), 1.f);
        bx.z = fminf(fmaxf(__fadd_rn(cx, __fmul_rn(0.5f,w)), 0.f), 1.f);
        bx.w = fminf(fmaxf(__fadd_rn(cy, __fmul_rn(0.5f,h)), 0.f), 1.f);
        g_boxes[(size_t)b*PRI + pb + tid] = bx;
    }
    for (int j = tid; j < NC*64; j += bd){
        int c = j >> 6, pl = j & 63;
        if (pl < cnt){
            float v = tile[pl*CDIM + 5 + c];
            g_keys[((size_t)(b*NC + c))*PRI + pb + pl] =
                (v > 0.01f) ? f2u(v) : 0x407FFFFFu;   // f2u(-1.0f)
        }
    }
}

// ---------------- bitonic sort (descending) over keys[0..M), M power of 2 ----------------
__device__ void bitonic_desc(unsigned long long* keys, int M){
    const int tid = threadIdx.x, bd = blockDim.x;
    for (int size = 2; size <= M; size <<= 1){
        for (int stride = size >> 1; stride > 0; stride >>= 1){
            __syncthreads();
            for (int i = tid; i < M; i += bd){
                int j = i ^ stride;
                if (j > i){
                    unsigned long long a = keys[i], b = keys[j];
                    bool up = ((i & size) == 0);
                    if (up ? (a < b) : (a > b)){ keys[i] = b; keys[j] = a; }
                }
            }
        }
    }
    __syncthreads();
}

// ---------------- block-wide exact top-K (sorted desc by (value,~index)), 512 threads --------
// whist: 4096 u32 scratch; keys: CAP u64 out. keys[0..K-1] valid after return.
__device__ void topk_sorted(const unsigned* __restrict__ g, int N, int K,
                            unsigned* whist, unsigned long long* keys)
{
    __shared__ unsigned suf[256];
    __shared__ unsigned wtot[8], wabove[8];
    __shared__ unsigned s_prefix;
    __shared__ int s_k, s_above, s_cand, s_stop, s_cnt, s_eq, s_eqbase;
    __shared__ int warpTot[16];
    const int tid = threadIdx.x, bd = blockDim.x;
    const int wid = tid >> 5, lane = tid & 31;

    if (tid == 0){ s_prefix = 0u; s_k = K; s_above = 0; s_stop = -100; s_cnt = 0; s_eq = 0; s_eqbase = 0; }
    for (int i = tid; i < CAP; i += bd) keys[i] = 0ULL;
    __syncthreads();

    // radix refinement with early exit when candidate set fits in CAP
    for (int shift = 24; shift >= 0; shift -= 8){
        for (int i = tid; i < 4096; i += bd) whist[i] = 0u;
        __syncthreads();
        unsigned pmask = (shift == 24) ? 0u : (0xFFFFFFFFu << (shift+8));
        unsigned pref  = s_prefix;
        unsigned* myh  = &whist[wid << 8];
        for (int i = tid; i < N; i += bd){
            unsigned v = g[i];
            if ((v & pmask) == pref) atomicAdd(&myh[(v >> shift) & 255u], 1u);
        }
        __syncthreads();
        if (tid < 256){
            unsigned s = 0;
            #pragma unroll
            for (int w = 0; w < 16; w++) s += whist[(w << 8) + tid];
            // warp-local suffix scan (towards higher bin index)
            #pragma unroll
            for (int off = 1; off < 32; off <<= 1){
                unsigned o = __shfl_down_sync(0xFFFFFFFFu, s, off);
                if (lane + off < 32) s += o;
            }
            suf[tid] = s;
            if (lane == 0) wtot[wid] = s;
        }
        __syncthreads();
        if (tid < 8){
            unsigned t = 0;
            for (int j = tid + 1; j < 8; j++) t += wtot[j];
            wabove[tid] = t;
        }
        __syncthreads();
        if (tid < 256){
            int here = (int)(suf[tid] + wabove[wid]);
            int abv  = (int)(((lane == 31) ? 0u : suf[tid+1]) + wabove[wid]);
            int k = s_k;
            if (here >= k && abv < k){            // unique crossing bin
                s_prefix = pref | ((unsigned)tid << shift);
                s_k = k - abv;
                int newAbove = s_above + abv;
                s_above = newAbove;
                int cand = newAbove + (here - abv);
                s_cand = cand;
                if (cand <= CAP || shift == 0) s_stop = shift;
            }
        }
        __syncthreads();
        if (s_stop != -100) break;
    }
    const int cand = s_cand;

    if (cand <= CAP){
        // fast path: compact all v >= prefix-base, sort, done (ties resolved by sort)
        unsigned Tb = s_prefix;   // bits below stop level are zero
        for (int i = tid; i < N; i += bd){
            unsigned v = g[i];
            if (v >= Tb){
                int pos = atomicAdd(&s_cnt, 1);
                keys[pos] = ((unsigned long long)v << 32) | (unsigned)(~(unsigned)i);
            }
        }
        __syncthreads();
        int M = (cand <= 512) ? 512 : ((cand <= 1024) ? 1024 : 2048);
        bitonic_desc(keys, M);
    } else {
        // fallback: stop==0, prefix is an exact 32-bit value with massive tie count
        const unsigned T = s_prefix;
        const int need = s_k, cntAbove = s_above;
        for (int i = tid; i < N; i += bd){
            unsigned v = g[i];
            if (v > T){
                int pos = atomicAdd(&s_cnt, 1);
                keys[pos] = ((unsigned long long)v << 32) | (unsigned)(~(unsigned)i);
            }
        }
        __syncthreads();
        // ordered (lowest index first) pick of `need` elements == T
        for (int base = 0; base < N && s_eqbase < need; base += bd){
            int i = base + tid;
            bool eq = (i < N) && (g[i] == T);
            unsigned ball = __ballot_sync(0xFFFFFFFFu, eq);
            int wpre = __popc(ball & ((1u << lane) - 1u));
            if (lane == 0) warpTot[wid] = __popc(ball);
            __syncthreads();
            int pre = 0;
            for (int w = 0; w < wid; w++) pre += warpTot[w];
            int rank = s_eqbase + pre + wpre;
            if (eq && rank < need)
                keys[cntAbove + rank] = ((unsigned long long)T << 32) | (unsigned)(~(unsigned)i);
            __syncthreads();
            if (tid == 0){ int tot = 0; for (int w = 0; w < 16; w++) tot += warpTot[w]; s_eqbase += tot; }
            __syncthreads();
        }
        __syncthreads();
        bitonic_desc(keys, 512);
    }
}

// ---------------- K2: fused per-(b,c) top-400 + greedy NMS ----------------
__global__ void __launch_bounds__(512) k_class(){
    __shared__ __align__(16) unsigned char smemA[32768];  // whist+keys, later smat
    __shared__ float4 sbox[TK1];
    __shared__ float  sarea[TK1];
    __shared__ float  sS[TK1];
    __shared__ unsigned long long skept[NWORD];
    unsigned*           whist = (unsigned*)smemA;
    unsigned long long* keys  = (unsigned long long*)(smemA + 16384);
    unsigned long long* smat  = (unsigned long long*)smemA;   // aliases whist+keys after selection

    int bc = blockIdx.x, b = bc / NC, c = bc % NC;
    int tid = threadIdx.x, bd = blockDim.x, wid = tid >> 5;

    topk_sorted(g_keys + (size_t)bc*PRI, PRI, TK1, whist, keys);

    for (int r = tid; r < TK1; r += bd){
        unsigned long long kk = keys[r];
        int idx  = (int)(~(unsigned)(kk & 0xFFFFFFFFu));
        float sc = u2f((unsigned)(kk >> 32));
        float4 bx = g_boxes[(size_t)b*PRI + idx];
        sbox[r] = bx; sS[r] = sc;
        sarea[r] = __fmul_rn(__fsub_rn(bx.z,bx.x), __fsub_rn(bx.w,bx.y));
        g_selIdx[bc*TK1 + r] = idx;
    }
    __syncthreads();   // keys fully consumed; smat may overwrite

    // lower-triangle suppression bitmatrix: bit (i,j) = iou(i,j) > 0.45, j < i
    for (int t = tid; t < TK1*NWORD; t += bd){
        int i = t / NWORD, w = t % NWORD;
        int j0 = w*64, j1 = min(i, j0 + 64);
        unsigned long long word = 0;
        if (j1 > j0){
            float4 a = sbox[i]; float ai = sarea[i];
            for (int j = j0; j < j1; j++){
                float4 d = sbox[j];
                float ix1 = fmaxf(a.x, d.x), iy1 = fmaxf(a.y, d.y);
                float ix2 = fminf(a.z, d.z), iy2 = fminf(a.w, d.w);
                float iw = fmaxf(__fsub_rn(ix2, ix1), 0.0f);
                float ih = fmaxf(__fsub_rn(iy2, iy1), 0.0f);
                float inter = __fmul_rn(iw, ih);
                bool gt = false;
                if (inter > 0.0f){
                    float uni = __fsub_rn(__fadd_rn(ai, sarea[j]), inter);
                    if (uni > 0.0f){
                        if (inter > 0.46f*uni)       gt = true;
                        else if (inter >= 0.44f*uni) gt = (__fdiv_rn(inter, uni) > 0.45f);
                    }
                }
                if (gt) word |= 1ULL << (j - j0);
            }
        }
        smat[i*NWORD + w] = word;
    }
    __syncthreads();

    // sequential greedy scan; scan-warp varies per block to spread across SMSPs
    int swid = blockIdx.x & 15;
    if (wid == swid){
        int lane = tid & 31;
        unsigned long long keptw = 0;
        unsigned long long row = (lane < NWORD) ? smat[lane] : 0ULL;
        float sc = sS[0];
        for (int i = 0; i < TK1; i++){
            unsigned long long nrow = 0ULL; float nsc = 0.f;
            if (i + 1 < TK1){
                if (lane < NWORD) nrow = smat[(i+1)*NWORD + lane];
                nsc = sS[i+1];
            }
            bool any = __any_sync(0xFFFFFFFFu, (row & keptw) != 0ULL);
            if (sc > 0.01f && !any && lane == (i >> 6)) keptw |= 1ULL << (i & 63);
            row = nrow; sc = nsc;
        }
        if (lane < NWORD) skept[lane] = keptw;
    }
    __syncthreads();

    for (int r = tid; r < TK1; r += bd){
        bool kept = (skept[r >> 6] >> (r & 63)) & 1ULL;
        float sc = kept ? sS[r] : -1.0f;
        g_detKey[(size_t)b*NDET + c*TK1 + r] = f2u(sc);
    }
}

// ---------------- K3: fused per-batch top-200 + rasterize ----------------
__global__ void __launch_bounds__(512) k_det_raster(float* __restrict__ out){
    __shared__ __align__(16) unsigned char smemA[32768];
    __shared__ float sS2[TK2];
    __shared__ int   sCh[TK2];
    __shared__ int4  sCo[TK2];
    __shared__ unsigned char sV[TK2];
    unsigned*           whist = (unsigned*)smemA;
    unsigned long long* keys  = (unsigned long long*)(smemA + 16384);
    int b = blockIdx.x, tid = threadIdx.x, bd = blockDim.x;

    topk_sorted(g_detKey + (size_t)b*NDET, NDET, TK2, whist, keys);

    for (int k = tid; k < TK2; k += bd){
        unsigned long long kk = keys[k];
        int fi   = (int)(~(unsigned)(kk & 0xFFFFFFFFu));
        float s  = u2f((unsigned)(kk >> 32));
        int c = fi / TK1, r = fi % TK1;
        int idx = g_selIdx[(b*NC + c)*TK1 + r];
        float4 bx = g_boxes[(size_t)b*PRI + idx];
        int4 co;
        co.x = (int)rintf(__fmul_rn(bx.x, (float)OGRID));
        co.y = (int)rintf(__fmul_rn(bx.y, (float)OGRID));
        co.z = (int)rintf(__fmul_rn(bx.z, (float)OGRID));
        co.w = (int)rintf(__fmul_rn(bx.w, (float)OGRID));
        sS2[k] = s; sCh[k] = c; sCo[k] = co; sV[k] = (s >= 0.6f) ? 1 : 0;
    }
    __syncthreads();

    for (int cell = tid; cell < OGRID*OGRID; cell += bd){
        int y = cell / OGRID, xp = cell % OGRID;
        float* o = out + ((size_t)b*OGRID*OGRID + cell) * 81;
        for (int ch = 0; ch < 81; ch++) o[ch] = 0.0f;
        for (int k = 0; k < TK2; k++){
            if (sV[k]){
                int4 co = sCo[k];
                if (y >= co.y && y < co.w && xp >= co.x && xp < co.z)
                    o[sCh[k]] = sS2[k];     // ascending k: last writer == max k
            }
        }
    }
}

// ---------------- launch ----------------
extern "C" void kernel_launch(void* const* d_in, const int* in_sizes, int n_in,
                              void* d_out, int out_size){
    const float* x = (const float*)d_in[0];
    float* out = (float*)d_out;
    dim3 g1((PRI + 63) / 64, BATCH);
    k_decode<<<g1, 128>>>(x);
    k_class<<<BATCH*NC, 512>>>();
    k_det_raster<<<BATCH, 512>>>(out);
}